// round 7
// baseline (speedup 1.0000x reference)
#include <cuda_runtime.h>

#define N_NODES 100000
#define N_EDGES 1600000

// Scratch (no cudaMalloc allowed). Ping-pong buffers A and B.
__device__ float A_buf[N_NODES * 32];
__device__ float B_buf[N_NODES * 32];
__device__ float dinv_buf[N_NODES];       // rsqrt(deg+1)
__device__ int   deg_buf[N_NODES];        // in-degree (zeroed by tail of final kernel)
__device__ int   row_start[N_NODES];      // CSR segment start (by dst, arbitrary order)
__device__ int   cursor_buf[N_NODES];     // fill cursors (init = row_start)
__device__ int   csr_src[N_EDGES];        // src grouped by dst
__device__ int   src32[N_EDGES];          // converted edge list
__device__ int   dst32[N_EDGES];
__device__ int   total_counter;           // segment allocator (zeroed by final kernel)

// ---------------- pass 1: convert int64/int32 -> int32, histogram dst ----------------
// dtype detect per block: int64 little-endian with ids < 2^31 has all odd words zero.
__global__ void conv_hist_kernel(const int* __restrict__ ei) {
    __shared__ int is64_sh;
    if (threadIdx.x == 0) {
        int any = 0;
        for (int k = 0; k < 64; k++) any |= ei[2 * k + 1];
        is64_sh = (any == 0) ? 1 : 0;
    }
    __syncthreads();
    int t = blockIdx.x * blockDim.x + threadIdx.x;
    if (t >= N_EDGES / 4) return;

    int4 s, d;
    if (is64_sh) {
        const int4* p = reinterpret_cast<const int4*>(ei);
        int4 s0 = p[2 * t], s1 = p[2 * t + 1];
        int4 d0 = p[N_EDGES / 2 + 2 * t], d1 = p[N_EDGES / 2 + 2 * t + 1];
        s = make_int4(s0.x, s0.z, s1.x, s1.z);
        d = make_int4(d0.x, d0.z, d1.x, d1.z);
    } else {
        s = reinterpret_cast<const int4*>(ei)[t];
        d = reinterpret_cast<const int4*>(ei + N_EDGES)[t];
    }
    reinterpret_cast<int4*>(src32)[t] = s;
    reinterpret_cast<int4*>(dst32)[t] = d;
    atomicAdd(&deg_buf[d.x], 1);
    atomicAdd(&deg_buf[d.y], 1);
    atomicAdd(&deg_buf[d.z], 1);
    atomicAdd(&deg_buf[d.w], 1);
}

__device__ __forceinline__ int block_inclusive_scan(int v, int tid) {
    __shared__ int warp_sums[32];
    int lane = tid & 31;
#pragma unroll
    for (int o = 1; o < 32; o <<= 1) {
        int n = __shfl_up_sync(0xffffffffu, v, o);
        if (lane >= o) v += n;
    }
    if (lane == 31) warp_sums[tid >> 5] = v;
    __syncthreads();
    if (tid < 32) {
        int w = warp_sums[tid];
#pragma unroll
        for (int o = 1; o < 32; o <<= 1) {
            int n = __shfl_up_sync(0xffffffffu, w, o);
            if (tid >= o) w += n;
        }
        warp_sums[tid] = w;
    }
    __syncthreads();
    return (tid >= 32) ? v + warp_sums[(tid >> 5) - 1] : v;
}

// Segment allocation (block scan + one atomic per block; cross-block order arbitrary)
// + cursor init + fused pad: A[i*32+c] = dinv[i]*x[i*18+c] (c<18), else 0.
__global__ void alloc_pad_kernel(const float* __restrict__ x) {
    int tid = threadIdx.x;
    int i = blockIdx.x * 1024 + tid;
    int v = (i < N_NODES) ? deg_buf[i] : 0;
    int inc = block_inclusive_scan(v, tid);
    __shared__ int base_sh;
    if (tid == 1023) base_sh = atomicAdd(&total_counter, inc);
    __syncthreads();
    if (i < N_NODES) {
        int rs = base_sh + inc - v;
        row_start[i] = rs;
        cursor_buf[i] = rs;
        float d = rsqrtf((float)(v + 1));
        dinv_buf[i] = d;
        float r[32];
#pragma unroll
        for (int c = 0; c < 18; c++) r[c] = d * x[i * 18 + c];
#pragma unroll
        for (int c = 18; c < 32; c++) r[c] = 0.0f;
        float4* a4 = reinterpret_cast<float4*>(&A_buf[i * 32]);
#pragma unroll
        for (int q = 0; q < 8; q++)
            a4[q] = make_float4(r[q * 4], r[q * 4 + 1], r[q * 4 + 2], r[q * 4 + 3]);
    }
}

// 4 edges per thread; reads compact int32 arrays (L2-resident after conv_hist)
__global__ void fill_kernel() {
    int t = blockIdx.x * blockDim.x + threadIdx.x;
    if (t >= N_EDGES / 4) return;
    int4 s = reinterpret_cast<const int4*>(src32)[t];
    int4 d = reinterpret_cast<const int4*>(dst32)[t];
    int p0 = atomicAdd(&cursor_buf[d.x], 1);
    int p1 = atomicAdd(&cursor_buf[d.y], 1);
    int p2 = atomicAdd(&cursor_buf[d.z], 1);
    int p3 = atomicAdd(&cursor_buf[d.w], 1);
    csr_src[p0] = s.x;
    csr_src[p1] = s.y;
    csr_src[p2] = s.z;
    csr_src[p3] = s.w;
}

// ---------------- layer 1 aggregation (pre-GEMM, 32-wide padded) ----------------
// B[i] = dinv[i] * (A[i] + sum_{s in N(i)} A[s])
__global__ void agg_pre_kernel() {
    int w = (blockIdx.x * blockDim.x + threadIdx.x) >> 5;
    if (w >= N_NODES) return;
    int lane = threadIdx.x & 31;
    float a = A_buf[w * 32 + lane];  // self loop
    int beg = row_start[w], end = beg + deg_buf[w];
#pragma unroll 8
    for (int k = beg; k < end; k++) {
        a += A_buf[csr_src[k] * 32 + lane];
    }
    B_buf[w * 32 + lane] = dinv_buf[w] * a;
}

// ---------------- fused GEMM1(+relu)+GEMM2: B(aggx,32-pad) -> A(g32) ----------------
__global__ void gemm12_kernel(const float* __restrict__ W1, const float* __restrict__ b1,
                              const float* __restrict__ W2) {
    __shared__ float W1t[64 * 20];
    __shared__ float W2s[64 * 32];
    __shared__ float b1s[64];
    for (int t = threadIdx.x; t < 18 * 64; t += blockDim.x) {
        int m = t / 64, k = t % 64;
        W1t[k * 20 + m] = W1[t];
    }
    for (int t = threadIdx.x; t < 64 * 32; t += blockDim.x) W2s[t] = W2[t];
    for (int t = threadIdx.x; t < 64; t += blockDim.x) b1s[t] = b1[t];
    __syncthreads();

    int i = blockIdx.x * blockDim.x + threadIdx.x;
    if (i >= N_NODES) return;

    float xr[18];
    const float4* x4 = reinterpret_cast<const float4*>(&B_buf[i * 32]);
#pragma unroll
    for (int q = 0; q < 4; q++) {
        float4 v = x4[q];
        xr[q * 4 + 0] = v.x; xr[q * 4 + 1] = v.y; xr[q * 4 + 2] = v.z; xr[q * 4 + 3] = v.w;
    }
    { float2 v = reinterpret_cast<const float2*>(&B_buf[i * 32])[8]; xr[16] = v.x; xr[17] = v.y; }

    float o[32];
#pragma unroll
    for (int j = 0; j < 32; j++) o[j] = 0.0f;

#pragma unroll 2
    for (int k = 0; k < 64; k++) {
        const float4* w1 = reinterpret_cast<const float4*>(&W1t[k * 20]);
        float acc = b1s[k];
#pragma unroll
        for (int q = 0; q < 4; q++) {
            float4 w = w1[q];
            acc += xr[q * 4 + 0] * w.x + xr[q * 4 + 1] * w.y
                 + xr[q * 4 + 2] * w.z + xr[q * 4 + 3] * w.w;
        }
        acc += xr[16] * W1t[k * 20 + 16] + xr[17] * W1t[k * 20 + 17];
        float h = fmaxf(acc, 0.0f);
        const float4* w2 = reinterpret_cast<const float4*>(&W2s[k * 32]);
#pragma unroll
        for (int q = 0; q < 8; q++) {
            float4 w = w2[q];
            o[q * 4 + 0] += h * w.x; o[q * 4 + 1] += h * w.y;
            o[q * 4 + 2] += h * w.z; o[q * 4 + 3] += h * w.w;
        }
    }
    float d = dinv_buf[i];
    float4* a4 = reinterpret_cast<float4*>(&A_buf[i * 32]);
#pragma unroll
    for (int q = 0; q < 8; q++)
        a4[q] = make_float4(d * o[q * 4], d * o[q * 4 + 1], d * o[q * 4 + 2], d * o[q * 4 + 3]);
}

// ---------------- layer 2 agg + fused GEMM3: A(g32) -> B(g16) ----------------
__global__ void agg32_g3_kernel(const float* __restrict__ b2, const float* __restrict__ W3) {
    __shared__ float W3s[32 * 16];
    for (int t = threadIdx.x; t < 32 * 16; t += blockDim.x) W3s[t] = W3[t];
    __syncthreads();

    int w = (blockIdx.x * blockDim.x + threadIdx.x) >> 5;
    if (w >= N_NODES) return;
    int lane = threadIdx.x & 31;
    float a = A_buf[w * 32 + lane];
    int beg = row_start[w], end = beg + deg_buf[w];
#pragma unroll 8
    for (int k = beg; k < end; k++) {
        a += A_buf[csr_src[k] * 32 + lane];
    }
    float d = dinv_buf[w];
    float h = fmaxf(fmaf(d, a, b2[lane]), 0.0f);

    float o = 0.0f;
    int j = lane & 15;
#pragma unroll
    for (int k = 0; k < 32; k++) {
        float hk = __shfl_sync(0xffffffffu, h, k);
        o += hk * W3s[k * 16 + j];
    }
    if (lane < 16) B_buf[w * 16 + lane] = d * o;
}

// ---------------- layer 3 agg + fused GEMM4: B(g16) -> A(g2) ----------------
__global__ void agg16_g4_kernel(const float* __restrict__ b3, const float* __restrict__ W4) {
    int t = blockIdx.x * blockDim.x + threadIdx.x;
    int i = t >> 4;
    if (i >= N_NODES) return;
    int c = t & 15;
    float a = B_buf[i * 16 + c];
    int beg = row_start[i], end = beg + deg_buf[i];
#pragma unroll 8
    for (int k = beg; k < end; k++) {
        a += B_buf[csr_src[k] * 16 + c];
    }
    float d = dinv_buf[i];
    float h = fmaxf(fmaf(d, a, b3[c]), 0.0f);

    float v0 = h * W4[c * 2 + 0];
    float v1 = h * W4[c * 2 + 1];
#pragma unroll
    for (int o = 8; o >= 1; o >>= 1) {
        v0 += __shfl_xor_sync(0xffffffffu, v0, o);
        v1 += __shfl_xor_sync(0xffffffffu, v1, o);
    }
    if (c == 0) {
        A_buf[i * 2 + 0] = d * v0;
        A_buf[i * 2 + 1] = d * v1;
    }
}

// ---------------- final: agg + bias + log_softmax + state cleanup ----------------
// Tail re-zeros deg_buf/total_counter so the next call starts from the static-init state.
__global__ void agg2_logsoftmax_kernel(const float* __restrict__ b, float* __restrict__ out) {
    int i = blockIdx.x * blockDim.x + threadIdx.x;
    if (i >= N_NODES) return;
    const float2* g2 = reinterpret_cast<const float2*>(A_buf);
    float2 a = g2[i];
    int beg = row_start[i], end = beg + deg_buf[i];
#pragma unroll 8
    for (int k = beg; k < end; k++) {
        float2 v = g2[csr_src[k]];
        a.x += v.x; a.y += v.y;
    }
    float d = dinv_buf[i];
    float v0 = fmaf(d, a.x, b[0]);
    float v1 = fmaf(d, a.y, b[1]);
    float m = fmaxf(v0, v1);
    float lse = m + logf(expf(v0 - m) + expf(v1 - m));
    out[i * 2 + 0] = v0 - lse;
    out[i * 2 + 1] = v1 - lse;

    // cleanup for next call (deterministic invariant restore)
    deg_buf[i] = 0;
    if (i == 0) total_counter = 0;
}

// ---------------- launch ----------------

extern "C" void kernel_launch(void* const* d_in, const int* in_sizes, int n_in,
                              void* d_out, int out_size) {
    const float* x  = (const float*)d_in[0];
    const int*   ei = (const int*)d_in[1];
    const float* W1 = (const float*)d_in[2];
    const float* b1 = (const float*)d_in[3];
    const float* W2 = (const float*)d_in[4];
    const float* b2 = (const float*)d_in[5];
    const float* W3 = (const float*)d_in[6];
    const float* b3 = (const float*)d_in[7];
    const float* W4 = (const float*)d_in[8];
    const float* b4 = (const float*)d_in[9];
    float* out = (float*)d_out;

    const int T = 256;
    const int nodeB = (N_NODES + T - 1) / T;
    const int quadEdgeB = (N_EDGES / 4 + T - 1) / T;
    const int warpNodeB = (N_NODES * 32 + T - 1) / T;

    // CSR build (group by dst)
    conv_hist_kernel<<<quadEdgeB, T>>>(ei);
    alloc_pad_kernel<<<(N_NODES + 1023) / 1024, 1024>>>(x);
    fill_kernel<<<quadEdgeB, T>>>();

    // Layer 1 agg (pre-GEMM), then fused GEMM1+relu+GEMM2
    agg_pre_kernel<<<warpNodeB, T>>>();
    gemm12_kernel<<<nodeB, T>>>(W1, b1, W2);

    // Layer 2 agg + fused GEMM3
    agg32_g3_kernel<<<warpNodeB, T>>>(b2, W3);

    // Layer 3 agg + fused GEMM4
    agg16_g4_kernel<<<(N_NODES * 16 + T - 1) / T, T>>>(b3, W4);

    // Layer 4 agg + log_softmax (+ cleanup)
    agg2_logsoftmax_kernel<<<nodeB, T>>>(b4, out);
}